// round 11
// baseline (speedup 1.0000x reference)
#include <cuda_runtime.h>
#include <cstdint>

#define BATCH   8
#define NPTS    16384
#define CH      13
#define NGROUP  512
#define KNN     32

#define FPS_CLUSTER 8
#define FPS_THREADS 256
#define FPS_CHUNK   (NPTS / FPS_CLUSTER)            // 2048 points per CTA
#define FPS_PPT     (FPS_CHUNK / FPS_THREADS)       // 8 points per thread
#define FPS_PAIRS   (FPS_PPT / 2)                   // 4 packed pairs

#define KT      512                 // knn threads per block
#define KPT     (NPTS / KT)         // 32 points per thread

#define NEIGH_ELEMS ((size_t)BATCH * NGROUP * KNN * CH)  // 1,703,936
#define CEN_ELEMS   ((size_t)BATCH * NGROUP * 3)         // 12,288

// Static device scratch (no allocation allowed).
__device__ float4 g_pts[BATCH * NPTS];          // x,y,z,pp  (2 MB)
__device__ float  g_centers[BATCH * NGROUP * 3];

// ---------------------------------------------------------------------------
// Prep: pack xyz (channels 4:7) + pp = ((x^2+y^2)+z^2) (non-FMA, XLA order)
// ---------------------------------------------------------------------------
__global__ void prep_kernel(const float* __restrict__ x) {
    int i = blockIdx.x * blockDim.x + threadIdx.x;
    if (i >= BATCH * NPTS) return;
    const float* p = x + (size_t)i * CH;
    float px = p[4], py = p[5], pz = p[6];
    float pp = __fadd_rn(__fadd_rn(__fmul_rn(px, px), __fmul_rn(py, py)),
                         __fmul_rn(pz, pz));
    g_pts[i] = make_float4(px, py, pz, pp);
}

__device__ __forceinline__ uint32_t smem_u32(const void* p) {
    return (uint32_t)__cvta_generic_to_shared(p);
}
__device__ __forceinline__ unsigned long long pack2(float a, float b) {
    unsigned long long r;
    asm("mov.b64 %0, {%1, %2};" : "=l"(r) : "f"(a), "f"(b));
    return r;
}
__device__ __forceinline__ unsigned long long addx2(unsigned long long a,
                                                    unsigned long long b) {
    unsigned long long r;
    asm("add.rn.f32x2 %0, %1, %2;" : "=l"(r) : "l"(a), "l"(b));
    return r;
}
__device__ __forceinline__ unsigned long long mulx2(unsigned long long a,
                                                    unsigned long long b) {
    unsigned long long r;
    asm("mul.rn.f32x2 %0, %1, %2;" : "=l"(r) : "l"(a), "l"(b));
    return r;
}
__device__ __forceinline__ uint32_t mapa_sh(uint32_t addr, uint32_t r) {
    uint32_t o;
    asm("mapa.shared::cluster.u32 %0, %1, %2;" : "=r"(o) : "r"(addr), "r"(r));
    return o;
}
__device__ __forceinline__ void dsm_st(uint32_t addr, unsigned long long v) {
    asm volatile("st.relaxed.cluster.shared::cluster.u64 [%0], %1;"
                 :: "r"(addr), "l"(v) : "memory");
}
__device__ __forceinline__ unsigned long long poll_ld(uint32_t addr) {
    unsigned long long v;
    asm volatile("ld.relaxed.cluster.shared::cta.u64 %0, [%1];"
                 : "=l"(v) : "r"(addr) : "memory");
    return v;
}

// ---------------------------------------------------------------------------
// FPS: one 8-CTA cluster per batch. Points (packed f32x2) + min_d (raw bits)
// in registers; distance math f32x2 rn (bit-identical per half to scalar rn).
// R9 skeleton (single __syncthreads/iter, self-tagged double-buffered 4-word
// slots, warp-0 lane-parallel publish, NO trailing barrier). Change under
// test: the poll is lane-parallel in EVERY warp — lane l spins on exactly
// one word (rank = l>>2, word = l&3), then redux/ballot picks the winning
// rank (lowest lane => smallest rank => smallest global index on ties) and
// shfls extract the coords. Replaces 8+3 sequential spin loops per thread.
// All tie-breaks ascending-index at every level => identical to jnp.argmax.
// ---------------------------------------------------------------------------
__global__ void __cluster_dims__(FPS_CLUSTER, 1, 1) __launch_bounds__(FPS_THREADS, 1)
fps_kernel() {
    __shared__ uint32_t s_wval[FPS_THREADS / 32];
    __shared__ int      s_widx[FPS_THREADS / 32];
    // rslot[parity][src_rank][word]: w0=(tag|val) w1=(tag|x) w2=(tag|y) w3=(tag|z)
    __shared__ unsigned long long rslot[2][FPS_CLUSTER][4];

    uint32_t rank;
    asm("mov.u32 %0, %%cluster_ctarank;" : "=r"(rank));
    int b = blockIdx.x / FPS_CLUSTER;
    int t = threadIdx.x, w = t >> 5, lane = t & 31;
    const float4* pts = g_pts + (size_t)b * NPTS;
    int base = (int)rank * FPS_CHUNK + t * FPS_PPT;

    // init all slot tags to an impossible value before any peer can store
    if (t < 2 * FPS_CLUSTER * 4) {
        ((unsigned long long*)rslot)[t] = ~0ull;
    }

    const uint32_t MD0 = __float_as_uint(1e10f);
    unsigned long long pxp[FPS_PAIRS], pyp[FPS_PAIRS], pzp[FPS_PAIRS];
    uint32_t md[FPS_PPT];
#pragma unroll
    for (int j = 0; j < FPS_PAIRS; j++) {
        float4 p0 = pts[base + 2 * j];
        float4 p1 = pts[base + 2 * j + 1];
        pxp[j] = pack2(p0.x, p1.x);
        pyp[j] = pack2(p0.y, p1.y);
        pzp[j] = pack2(p0.z, p1.z);
        md[2 * j] = MD0;
        md[2 * j + 1] = MD0;
    }

    float4 p00 = pts[0];
    float lx = p00.x, ly = p00.y, lz = p00.z;
    float* cout = g_centers + (size_t)b * NGROUP * 3;
    if (rank == 0 && t == 0) { cout[0] = lx; cout[1] = ly; cout[2] = lz; }

    // one-time cluster barrier: slot init must complete before any peer store
    asm volatile("barrier.cluster.arrive.aligned;" ::: "memory");
    asm volatile("barrier.cluster.wait.aligned;" ::: "memory");

    const int my_rk = lane >> 2;     // rank this lane targets / polls
    const int my_wd = lane & 3;      // word this lane builds / polls

    for (int g = 1; g < NGROUP; g++) {
        int p = g & 1;
        unsigned long long tag = ((unsigned long long)(uint32_t)g) << 32;
        unsigned long long nlx2 = pack2(-lx, -lx);
        unsigned long long nly2 = pack2(-ly, -ly);
        unsigned long long nlz2 = pack2(-lz, -lz);
        uint32_t bv = 0; int bk = base;
#pragma unroll
        for (int j = 0; j < FPS_PAIRS; j++) {
            unsigned long long dx2 = addx2(pxp[j], nlx2);
            unsigned long long dy2 = addx2(pyp[j], nly2);
            unsigned long long dz2 = addx2(pzp[j], nlz2);
            unsigned long long dd  = addx2(addx2(mulx2(dx2, dx2), mulx2(dy2, dy2)),
                                           mulx2(dz2, dz2));
            uint32_t d0 = (uint32_t)dd, d1 = (uint32_t)(dd >> 32);
            uint32_t m0 = umin(md[2 * j], d0);
            md[2 * j] = m0;
            if (m0 > bv) { bv = m0; bk = base + 2 * j; }
            uint32_t m1 = umin(md[2 * j + 1], d1);
            md[2 * j + 1] = m1;
            if (m1 > bv) { bv = m1; bk = base + 2 * j + 1; }
        }
        // warp winner: value via redux, index via ballot (lane order == idx order)
        uint32_t wv = __reduce_max_sync(0xFFFFFFFFu, bv);
        uint32_t mm = __ballot_sync(0xFFFFFFFFu, bv == wv);
        int leader = __ffs((int)mm) - 1;
        int wi = __shfl_sync(0xFFFFFFFFu, bk, leader);
        if (lane == 0) { s_wval[w] = wv; s_widx[w] = wi; }
        __syncthreads();

        if (w == 0) {
            // all 32 lanes redundantly scan the 8 warp winners (broadcast LDS);
            // ascending warp order + strict > => smallest idx on value tie
            uint32_t cv = s_wval[0]; int ci = s_widx[0];
#pragma unroll
            for (int i = 1; i < FPS_THREADS / 32; i++)
                if (s_wval[i] > cv) { cv = s_wval[i]; ci = s_widx[i]; }
            float4 cp = pts[ci];     // own chunk -> L1-resident, broadcast addr
            unsigned long long word;
            if      (my_wd == 0) word = tag | cv;
            else if (my_wd == 1) word = tag | __float_as_uint(cp.x);
            else if (my_wd == 2) word = tag | __float_as_uint(cp.y);
            else                 word = tag | __float_as_uint(cp.z);
            uint32_t la = smem_u32(&rslot[p][rank][my_wd]);
            dsm_st(mapa_sh(la, (uint32_t)my_rk), word);   // one store per lane
        }

        // lane-parallel poll (ALL warps, independent/redundant):
        // lane l spins on word (rank l>>2, word l&3) of the LOCAL slot slab
        uint32_t ap = smem_u32(&rslot[p][my_rk][my_wd]);
        unsigned long long pw;
        do { pw = poll_ld(ap); } while ((uint32_t)(pw >> 32) != (uint32_t)g);
        uint32_t payload = (uint32_t)pw;
        // winner rank: max over val lanes (my_wd==0), lowest set lane on tie
        // => smallest rank => smallest global index (ranks cover asc. chunks)
        uint32_t cval = (my_wd == 0) ? payload : 0u;
        uint32_t rv = __reduce_max_sync(0xFFFFFFFFu, cval);
        uint32_t rm = __ballot_sync(0xFFFFFFFFu, (my_wd == 0) && (cval == rv));
        int rr = (__ffs((int)rm) - 1) >> 2;
        lx = __uint_as_float(__shfl_sync(0xFFFFFFFFu, payload, rr * 4 + 1));
        ly = __uint_as_float(__shfl_sync(0xFFFFFFFFu, payload, rr * 4 + 2));
        lz = __uint_as_float(__shfl_sync(0xFFFFFFFFu, payload, rr * 4 + 3));

        if (rank == 0 && t == 0) {
            cout[3 * g] = lx; cout[3 * g + 1] = ly; cout[3 * g + 2] = lz;
        }
    }
}

// ---------------------------------------------------------------------------
// KNN + gather (unchanged: rel_err == 0 with this exact code).
// ---------------------------------------------------------------------------
__global__ void __launch_bounds__(KT)
knn_kernel(const float* __restrict__ x, float* __restrict__ out_neigh) {
    extern __shared__ uint32_t skey[];          // NPTS ordered keys (64 KB)
    __shared__ uint32_t wk[KT / 32];
    __shared__ uint32_t wi[KT / 32];
    __shared__ uint32_t sel[KNN];
    __shared__ uint32_t s_win;

    int b  = blockIdx.y;
    int gq = blockIdx.x;
    int t = threadIdx.x, w = t >> 5, lane = t & 31;
    const float4* pts = g_pts + (size_t)b * NPTS;
    const float* c3 = g_centers + ((size_t)b * NGROUP + gq) * 3;
    float cx = c3[0], cy = c3[1], cz = c3[2];
    float cc = __fadd_rn(__fadd_rn(__fmul_rn(cx, cx), __fmul_rn(cy, cy)),
                         __fmul_rn(cz, cz));

    uint32_t tk = 0xFFFFFFFFu, ti = 0xFFFFFFFFu;
#pragma unroll
    for (int kk = 0; kk < KPT; kk++) {
        int i = kk * KT + t;
        float4 p = pts[i];
        float dot = __fmaf_rn(cz, p.z, __fmaf_rn(cy, p.y, __fmul_rn(cx, p.x)));
        float d2  = __fsub_rn(__fadd_rn(cc, p.w), __fmul_rn(2.0f, dot));
        uint32_t u = __float_as_uint(d2);
        uint32_t o = u ^ (uint32_t)(((int)u >> 31) | 0x80000000);
        skey[i] = o;
        if (o < tk) { tk = o; ti = (uint32_t)i; }
    }
    {
        uint32_t rk = tk, ri = ti;
#pragma unroll
        for (int off = 16; off > 0; off >>= 1) {
            uint32_t ok = __shfl_down_sync(0xFFFFFFFFu, rk, off);
            uint32_t oi = __shfl_down_sync(0xFFFFFFFFu, ri, off);
            if (ok < rk || (ok == rk && oi < ri)) { rk = ok; ri = oi; }
        }
        if (lane == 0) { wk[w] = rk; wi[w] = ri; }
    }
    __syncthreads();

    for (int j = 0; j < KNN; j++) {
        if (w == 0) {
            uint32_t ak = (lane < KT / 32) ? wk[lane] : 0xFFFFFFFFu;
            uint32_t ai = (lane < KT / 32) ? wi[lane] : 0xFFFFFFFFu;
#pragma unroll
            for (int off = 16; off > 0; off >>= 1) {
                uint32_t ok = __shfl_down_sync(0xFFFFFFFFu, ak, off);
                uint32_t oi = __shfl_down_sync(0xFFFFFFFFu, ai, off);
                if (ok < ak || (ok == ak && oi < ai)) { ak = ok; ai = oi; }
            }
            if (lane == 0) { sel[j] = ai; s_win = ai; }
        }
        __syncthreads();
        uint32_t widx = s_win;
        int owner = (int)(widx & (KT - 1));
        if (t == owner) {
            skey[widx] = 0xFFFFFFFFu;
            tk = 0xFFFFFFFFu; ti = 0xFFFFFFFFu;
#pragma unroll
            for (int kk = 0; kk < KPT; kk++) {
                int i = kk * KT + t;
                uint32_t o = skey[i];
                if (o < tk) { tk = o; ti = (uint32_t)i; }
            }
        }
        if (w == (owner >> 5)) {
            uint32_t rk = tk, ri = ti;
#pragma unroll
            for (int off = 16; off > 0; off >>= 1) {
                uint32_t ok = __shfl_down_sync(0xFFFFFFFFu, rk, off);
                uint32_t oi = __shfl_down_sync(0xFFFFFFFFu, ri, off);
                if (ok < rk || (ok == rk && oi < ri)) { rk = ok; ri = oi; }
            }
            if (lane == 0) { wk[w] = rk; wi[w] = ri; }
        }
        __syncthreads();
    }

    if (t < KNN * CH) {
        int jj = t / CH, c = t % CH;
        uint32_t idx = sel[jj];
        float v = x[((size_t)b * NPTS + idx) * CH + c];
        if (c >= 4 && c < 7) {
            float cv = (c == 4) ? cx : ((c == 5) ? cy : cz);
            v = __fadd_rn(v, -cv);
        }
        out_neigh[(((size_t)b * NGROUP + gq) * KNN + jj) * CH + c] = v;
    }
}

// Copy centers scratch -> output tail
__global__ void centers_out_kernel(float* __restrict__ out_cen) {
    int i = blockIdx.x * blockDim.x + threadIdx.x;
    if (i < (int)CEN_ELEMS) out_cen[i] = g_centers[i];
}

extern "C" void kernel_launch(void* const* d_in, const int* in_sizes, int n_in,
                              void* d_out, int out_size) {
    const float* x = (const float*)d_in[0];
    float* out = (float*)d_out;

    cudaFuncSetAttribute(knn_kernel, cudaFuncAttributeMaxDynamicSharedMemorySize,
                         NPTS * sizeof(uint32_t));

    prep_kernel<<<(BATCH * NPTS + 255) / 256, 256>>>(x);
    fps_kernel<<<BATCH * FPS_CLUSTER, FPS_THREADS>>>();
    knn_kernel<<<dim3(NGROUP, BATCH), KT, NPTS * sizeof(uint32_t)>>>(x, out);
    if ((size_t)out_size >= NEIGH_ELEMS + CEN_ELEMS) {
        centers_out_kernel<<<((int)CEN_ELEMS + 255) / 256, 256>>>(out + NEIGH_ELEMS);
    }
}

// round 12
// speedup vs baseline: 1.4965x; 1.4965x over previous
#include <cuda_runtime.h>
#include <cstdint>

#define BATCH   8
#define NPTS    16384
#define CH      13
#define NGROUP  512
#define KNN     32

#define FPS_CLUSTER 8
#define FPS_THREADS 256
#define FPS_CHUNK   (NPTS / FPS_CLUSTER)            // 2048 points per CTA
#define FPS_PPT     (FPS_CHUNK / FPS_THREADS)       // 8 points per thread
#define FPS_PAIRS   (FPS_PPT / 2)                   // 4 packed pairs

#define KT       512                // knn threads per block
#define KPT      (NPTS / KT)        // 32 points per thread
#define KSTRIDE  33                 // padded stripe length (conflict-free)

#define NEIGH_ELEMS ((size_t)BATCH * NGROUP * KNN * CH)  // 1,703,936
#define CEN_ELEMS   ((size_t)BATCH * NGROUP * 3)         // 12,288

// Static device scratch (no allocation allowed).
__device__ float4 g_pts[BATCH * NPTS];          // x,y,z,pp  (2 MB)
__device__ float  g_centers[BATCH * NGROUP * 3];

// ---------------------------------------------------------------------------
// Prep: pack xyz (channels 4:7) + pp = ((x^2+y^2)+z^2) (non-FMA, XLA order)
// ---------------------------------------------------------------------------
__global__ void prep_kernel(const float* __restrict__ x) {
    int i = blockIdx.x * blockDim.x + threadIdx.x;
    if (i >= BATCH * NPTS) return;
    const float* p = x + (size_t)i * CH;
    float px = p[4], py = p[5], pz = p[6];
    float pp = __fadd_rn(__fadd_rn(__fmul_rn(px, px), __fmul_rn(py, py)),
                         __fmul_rn(pz, pz));
    g_pts[i] = make_float4(px, py, pz, pp);
}

__device__ __forceinline__ uint32_t smem_u32(const void* p) {
    return (uint32_t)__cvta_generic_to_shared(p);
}
__device__ __forceinline__ unsigned long long pack2(float a, float b) {
    unsigned long long r;
    asm("mov.b64 %0, {%1, %2};" : "=l"(r) : "f"(a), "f"(b));
    return r;
}
__device__ __forceinline__ unsigned long long addx2(unsigned long long a,
                                                    unsigned long long b) {
    unsigned long long r;
    asm("add.rn.f32x2 %0, %1, %2;" : "=l"(r) : "l"(a), "l"(b));
    return r;
}
__device__ __forceinline__ unsigned long long mulx2(unsigned long long a,
                                                    unsigned long long b) {
    unsigned long long r;
    asm("mul.rn.f32x2 %0, %1, %2;" : "=l"(r) : "l"(a), "l"(b));
    return r;
}
__device__ __forceinline__ uint32_t mapa_sh(uint32_t addr, uint32_t r) {
    uint32_t o;
    asm("mapa.shared::cluster.u32 %0, %1, %2;" : "=r"(o) : "r"(addr), "r"(r));
    return o;
}
__device__ __forceinline__ void dsm_st(uint32_t addr, unsigned long long v) {
    asm volatile("st.relaxed.cluster.shared::cluster.u64 [%0], %1;"
                 :: "r"(addr), "l"(v) : "memory");
}
__device__ __forceinline__ unsigned long long poll_ld(uint32_t addr) {
    unsigned long long v;
    asm volatile("ld.relaxed.cluster.shared::cta.u64 %0, [%1];"
                 : "=l"(v) : "r"(addr) : "memory");
    return v;
}

// ---------------------------------------------------------------------------
// FPS: FROZEN at the R9 configuration (649us, rel_err 0): single
// __syncthreads/iter, self-tagged double-buffered 4-word slots, warp-0
// lane-parallel publish, serial per-thread poll, no trailing barrier.
// ---------------------------------------------------------------------------
__global__ void __cluster_dims__(FPS_CLUSTER, 1, 1) __launch_bounds__(FPS_THREADS, 1)
fps_kernel() {
    __shared__ uint32_t s_wval[FPS_THREADS / 32];
    __shared__ int      s_widx[FPS_THREADS / 32];
    // rslot[parity][src_rank][word]: w0=(tag|val) w1=(tag|x) w2=(tag|y) w3=(tag|z)
    __shared__ unsigned long long rslot[2][FPS_CLUSTER][4];

    uint32_t rank;
    asm("mov.u32 %0, %%cluster_ctarank;" : "=r"(rank));
    int b = blockIdx.x / FPS_CLUSTER;
    int t = threadIdx.x, w = t >> 5, lane = t & 31;
    const float4* pts = g_pts + (size_t)b * NPTS;
    int base = (int)rank * FPS_CHUNK + t * FPS_PPT;

    // init all slot tags to an impossible value before any peer can store
    if (t < 2 * FPS_CLUSTER * 4) {
        ((unsigned long long*)rslot)[t] = ~0ull;
    }

    const uint32_t MD0 = __float_as_uint(1e10f);
    unsigned long long pxp[FPS_PAIRS], pyp[FPS_PAIRS], pzp[FPS_PAIRS];
    uint32_t md[FPS_PPT];
#pragma unroll
    for (int j = 0; j < FPS_PAIRS; j++) {
        float4 p0 = pts[base + 2 * j];
        float4 p1 = pts[base + 2 * j + 1];
        pxp[j] = pack2(p0.x, p1.x);
        pyp[j] = pack2(p0.y, p1.y);
        pzp[j] = pack2(p0.z, p1.z);
        md[2 * j] = MD0;
        md[2 * j + 1] = MD0;
    }

    float4 p00 = pts[0];
    float lx = p00.x, ly = p00.y, lz = p00.z;
    float* cout = g_centers + (size_t)b * NGROUP * 3;
    if (rank == 0 && t == 0) { cout[0] = lx; cout[1] = ly; cout[2] = lz; }

    // one-time cluster barrier: slot init must complete before any peer store
    asm volatile("barrier.cluster.arrive.aligned;" ::: "memory");
    asm volatile("barrier.cluster.wait.aligned;" ::: "memory");

    const int my_rk = lane >> 2;     // rank this lane targets (publish)
    const int my_wd = lane & 3;      // word this lane builds (publish)

    for (int g = 1; g < NGROUP; g++) {
        int p = g & 1;
        unsigned long long tag = ((unsigned long long)(uint32_t)g) << 32;
        unsigned long long nlx2 = pack2(-lx, -lx);
        unsigned long long nly2 = pack2(-ly, -ly);
        unsigned long long nlz2 = pack2(-lz, -lz);
        uint32_t bv = 0; int bk = base;
#pragma unroll
        for (int j = 0; j < FPS_PAIRS; j++) {
            unsigned long long dx2 = addx2(pxp[j], nlx2);
            unsigned long long dy2 = addx2(pyp[j], nly2);
            unsigned long long dz2 = addx2(pzp[j], nlz2);
            unsigned long long dd  = addx2(addx2(mulx2(dx2, dx2), mulx2(dy2, dy2)),
                                           mulx2(dz2, dz2));
            uint32_t d0 = (uint32_t)dd, d1 = (uint32_t)(dd >> 32);
            uint32_t m0 = umin(md[2 * j], d0);
            md[2 * j] = m0;
            if (m0 > bv) { bv = m0; bk = base + 2 * j; }
            uint32_t m1 = umin(md[2 * j + 1], d1);
            md[2 * j + 1] = m1;
            if (m1 > bv) { bv = m1; bk = base + 2 * j + 1; }
        }
        // warp winner: value via redux, index via ballot (lane order == idx order)
        uint32_t wv = __reduce_max_sync(0xFFFFFFFFu, bv);
        uint32_t mm = __ballot_sync(0xFFFFFFFFu, bv == wv);
        int leader = __ffs((int)mm) - 1;
        int wi = __shfl_sync(0xFFFFFFFFu, bk, leader);
        if (lane == 0) { s_wval[w] = wv; s_widx[w] = wi; }
        __syncthreads();

        if (w == 0) {
            // all 32 lanes redundantly scan the 8 warp winners (broadcast LDS);
            // ascending warp order + strict > => smallest idx on value tie
            uint32_t cv = s_wval[0]; int ci = s_widx[0];
#pragma unroll
            for (int i = 1; i < FPS_THREADS / 32; i++)
                if (s_wval[i] > cv) { cv = s_wval[i]; ci = s_widx[i]; }
            float4 cp = pts[ci];     // own chunk -> L1-resident, broadcast addr
            unsigned long long word;
            if      (my_wd == 0) word = tag | cv;
            else if (my_wd == 1) word = tag | __float_as_uint(cp.x);
            else if (my_wd == 2) word = tag | __float_as_uint(cp.y);
            else                 word = tag | __float_as_uint(cp.z);
            uint32_t la = smem_u32(&rslot[p][rank][my_wd]);
            dsm_st(mapa_sh(la, (uint32_t)my_rk), word);   // one store per lane
        }

        // poll all ranks' val words (ALL threads, serial — empirically fastest);
        // ascending rank + strict > => smallest global index on value ties
        uint32_t bestv = 0; int bestr = 0;
#pragma unroll
        for (int r = 0; r < FPS_CLUSTER; r++) {
            uint32_t ap = smem_u32(&rslot[p][r][0]);
            unsigned long long pl;
            do { pl = poll_ld(ap); } while ((uint32_t)(pl >> 32) != (uint32_t)g);
            uint32_t v = (uint32_t)pl;
            if (v > bestv) { bestv = v; bestr = r; }
        }
        // fetch winner coords (each word self-tagged -> no ordering needed)
        {
            uint32_t ab = smem_u32(&rslot[p][bestr][0]);
            unsigned long long w1, w2, w3;
            do { w1 = poll_ld(ab + 8);  } while ((uint32_t)(w1 >> 32) != (uint32_t)g);
            do { w2 = poll_ld(ab + 16); } while ((uint32_t)(w2 >> 32) != (uint32_t)g);
            do { w3 = poll_ld(ab + 24); } while ((uint32_t)(w3 >> 32) != (uint32_t)g);
            lx = __uint_as_float((uint32_t)w1);
            ly = __uint_as_float((uint32_t)w2);
            lz = __uint_as_float((uint32_t)w3);
        }
        if (rank == 0 && t == 0) {
            cout[3 * g] = lx; cout[3 * g + 1] = ly; cout[3 * g + 2] = lz;
        }
    }
}

// ---------------------------------------------------------------------------
// KNN + gather. Distance math / key encoding unchanged (rel_err 0 proven).
// NEW selection: keys stored transposed (pad-17 stripes skey[t*33+kk]);
// per-thread (min,idx) packed u64 in smem; warp 0 alone runs all 32
// selection iterations with redux.min pairs (key asc, then idx asc) and
// conflict-free stripe rescans — ZERO block barriers inside the loop.
// Tie-break = lexicographic (d2 asc, idx asc) at every level == lax.top_k.
// ---------------------------------------------------------------------------
__global__ void __launch_bounds__(KT)
knn_kernel(const float* __restrict__ x, float* __restrict__ out_neigh,
           float* __restrict__ out_cen) {
    extern __shared__ uint32_t skey[];            // KT*KSTRIDE keys (67.6 KB)
    __shared__ unsigned long long tpack[17 * 32]; // pos(t) = (t&15) + 17*(t>>4)
    __shared__ uint32_t sel[KNN];

    int b  = blockIdx.y;
    int gq = blockIdx.x;
    int t = threadIdx.x, w = t >> 5, lane = t & 31;
    const float4* pts = g_pts + (size_t)b * NPTS;
    const float* c3 = g_centers + ((size_t)b * NGROUP + gq) * 3;
    float cx = c3[0], cy = c3[1], cz = c3[2];
    float cc = __fadd_rn(__fadd_rn(__fmul_rn(cx, cx), __fmul_rn(cy, cy)),
                         __fmul_rn(cz, cz));

    uint32_t tk = 0xFFFFFFFFu, ti = 0xFFFFFFFFu;
#pragma unroll
    for (int kk = 0; kk < KPT; kk++) {
        int i = kk * KT + t;
        float4 p = pts[i];
        float dot = __fmaf_rn(cz, p.z, __fmaf_rn(cy, p.y, __fmul_rn(cx, p.x)));
        float d2  = __fsub_rn(__fadd_rn(cc, p.w), __fmul_rn(2.0f, dot));
        uint32_t u = __float_as_uint(d2);
        uint32_t o = u ^ (uint32_t)(((int)u >> 31) | 0x80000000);
        skey[t * KSTRIDE + kk] = o;                  // transposed stripe
        if (o < tk) { tk = o; ti = (uint32_t)i; }    // strict <, i ascending
    }
    tpack[(t & 15) + 17 * (t >> 4)] =
        ((unsigned long long)tk << 32) | (unsigned long long)ti;
    __syncthreads();

    if (w == 0) {
        // lane l caches lex-min of segment l (threads l*16 .. l*16+15)
        uint32_t ck = 0xFFFFFFFFu, ci = 0xFFFFFFFFu;
#pragma unroll
        for (int m = 0; m < 16; m++) {
            unsigned long long e = tpack[m + 17 * lane];
            uint32_t k = (uint32_t)(e >> 32), ii = (uint32_t)e;
            if (k < ck || (k == ck && ii < ci)) { ck = k; ci = ii; }
        }
        for (int j = 0; j < KNN; j++) {
            uint32_t kstar = __reduce_min_sync(0xFFFFFFFFu, ck);
            uint32_t istar = __reduce_min_sync(0xFFFFFFFFu,
                                (ck == kstar) ? ci : 0xFFFFFFFFu);
            int tstar = (int)(istar & (KT - 1));
            int kkst  = (int)(istar >> 9);
            if (lane == 0) {
                sel[j] = istar;
                skey[tstar * KSTRIDE + kkst] = 0xFFFFFFFFu;   // remove
            }
            __syncwarp();
            // rescan winner thread's 32-key stripe (conflict-free LDS)
            uint32_t v = skey[tstar * KSTRIDE + lane];
            uint32_t mk = __reduce_min_sync(0xFFFFFFFFu, v);
            uint32_t mi = __reduce_min_sync(0xFFFFFFFFu,
                            (v == mk) ? (uint32_t)(lane * KT + tstar)
                                      : 0xFFFFFFFFu);
            int sstar = tstar >> 4;
            if (lane == 0)
                tpack[(tstar & 15) + 17 * sstar] =
                    ((unsigned long long)mk << 32) | (unsigned long long)mi;
            // refresh segment sstar's cached min (substitute tstar in-register)
            uint32_t sk = 0xFFFFFFFFu, si = 0xFFFFFFFFu;
            if (lane < 16) {
                unsigned long long e = tpack[lane + 17 * sstar];
                sk = (uint32_t)(e >> 32); si = (uint32_t)e;
                if ((sstar * 16 + lane) == tstar) { sk = mk; si = mi; }
            }
            uint32_t nk = __reduce_min_sync(0xFFFFFFFFu, sk);
            uint32_t ni = __reduce_min_sync(0xFFFFFFFFu,
                            (sk == nk) ? si : 0xFFFFFFFFu);
            if (lane == sstar) { ck = nk; ci = ni; }
            __syncwarp();
        }
    }
    __syncthreads();

    // gather 32 x 13 features; channels 4..6 get (+ (-center))
    if (t < KNN * CH) {
        int jj = t / CH, c = t % CH;
        uint32_t idx = sel[jj];
        float v = x[((size_t)b * NPTS + idx) * CH + c];
        if (c >= 4 && c < 7) {
            float cv = (c == 4) ? cx : ((c == 5) ? cy : cz);
            v = __fadd_rn(v, -cv);
        }
        out_neigh[(((size_t)b * NGROUP + gq) * KNN + jj) * CH + c] = v;
    } else if (t >= KNN * CH && t < KNN * CH + 3 && out_cen != nullptr) {
        int c = t - KNN * CH;
        out_cen[((size_t)b * NGROUP + gq) * 3 + c] = c3[c];
    }
}

extern "C" void kernel_launch(void* const* d_in, const int* in_sizes, int n_in,
                              void* d_out, int out_size) {
    const float* x = (const float*)d_in[0];
    float* out = (float*)d_out;
    float* out_cen = ((size_t)out_size >= NEIGH_ELEMS + CEN_ELEMS)
                         ? (out + NEIGH_ELEMS) : nullptr;

    cudaFuncSetAttribute(knn_kernel, cudaFuncAttributeMaxDynamicSharedMemorySize,
                         KT * KSTRIDE * sizeof(uint32_t));

    prep_kernel<<<(BATCH * NPTS + 255) / 256, 256>>>(x);
    fps_kernel<<<BATCH * FPS_CLUSTER, FPS_THREADS>>>();
    knn_kernel<<<dim3(NGROUP, BATCH), KT, KT * KSTRIDE * sizeof(uint32_t)>>>(
        x, out, out_cen);
}

// round 13
// speedup vs baseline: 1.7671x; 1.1808x over previous
#include <cuda_runtime.h>
#include <cstdint>

#define BATCH   8
#define NPTS    16384
#define CH      13
#define NGROUP  512
#define KNN     32

#define FPS_CLUSTER 8
#define FPS_THREADS 256
#define FPS_CHUNK   (NPTS / FPS_CLUSTER)            // 2048 points per CTA
#define FPS_PPT     (FPS_CHUNK / FPS_THREADS)       // 8 points per thread
#define FPS_PAIRS   (FPS_PPT / 2)                   // 4 packed pairs

#define KT      512                 // knn threads per block
#define KPT     (NPTS / KT)         // 32 points per thread

#define NEIGH_ELEMS ((size_t)BATCH * NGROUP * KNN * CH)  // 1,703,936
#define CEN_ELEMS   ((size_t)BATCH * NGROUP * 3)         // 12,288

// Static device scratch (no allocation allowed).
__device__ float4 g_pts[BATCH * NPTS];          // x,y,z,pp  (2 MB)
__device__ float  g_centers[BATCH * NGROUP * 3];

// ---------------------------------------------------------------------------
// Prep: pack xyz (channels 4:7) + pp = ((x^2+y^2)+z^2) (non-FMA, XLA order)
// ---------------------------------------------------------------------------
__global__ void prep_kernel(const float* __restrict__ x) {
    int i = blockIdx.x * blockDim.x + threadIdx.x;
    if (i >= BATCH * NPTS) return;
    const float* p = x + (size_t)i * CH;
    float px = p[4], py = p[5], pz = p[6];
    float pp = __fadd_rn(__fadd_rn(__fmul_rn(px, px), __fmul_rn(py, py)),
                         __fmul_rn(pz, pz));
    g_pts[i] = make_float4(px, py, pz, pp);
}

__device__ __forceinline__ uint32_t smem_u32(const void* p) {
    return (uint32_t)__cvta_generic_to_shared(p);
}
__device__ __forceinline__ unsigned long long pack2(float a, float b) {
    unsigned long long r;
    asm("mov.b64 %0, {%1, %2};" : "=l"(r) : "f"(a), "f"(b));
    return r;
}
__device__ __forceinline__ unsigned long long addx2(unsigned long long a,
                                                    unsigned long long b) {
    unsigned long long r;
    asm("add.rn.f32x2 %0, %1, %2;" : "=l"(r) : "l"(a), "l"(b));
    return r;
}
__device__ __forceinline__ unsigned long long mulx2(unsigned long long a,
                                                    unsigned long long b) {
    unsigned long long r;
    asm("mul.rn.f32x2 %0, %1, %2;" : "=l"(r) : "l"(a), "l"(b));
    return r;
}
__device__ __forceinline__ uint32_t mapa_sh(uint32_t addr, uint32_t r) {
    uint32_t o;
    asm("mapa.shared::cluster.u32 %0, %1, %2;" : "=r"(o) : "r"(addr), "r"(r));
    return o;
}
__device__ __forceinline__ void dsm_st(uint32_t addr, unsigned long long v) {
    asm volatile("st.relaxed.cluster.shared::cluster.u64 [%0], %1;"
                 :: "r"(addr), "l"(v) : "memory");
}
__device__ __forceinline__ unsigned long long poll_ld(uint32_t addr) {
    unsigned long long v;
    asm volatile("ld.relaxed.cluster.shared::cta.u64 %0, [%1];"
                 : "=l"(v) : "r"(addr) : "memory");
    return v;
}

// ---------------------------------------------------------------------------
// FPS: FROZEN at the R9 configuration (best measured: 649us, rel_err 0):
// one 8-CTA cluster per batch; points (packed f32x2) + min_d (raw bits) in
// registers; f32x2 rn math (bit-identical per half to scalar rn); single
// __syncthreads/iter; self-tagged double-buffered 4-word DSMEM slots; warp-0
// lane-parallel publish (one tagged word per lane); serial per-thread poll
// (empirically faster than every warp-collective variant tried); no trailing
// barrier. All tie-breaks ascending-index => identical to jnp.argmax.
// ---------------------------------------------------------------------------
__global__ void __cluster_dims__(FPS_CLUSTER, 1, 1) __launch_bounds__(FPS_THREADS, 1)
fps_kernel() {
    __shared__ uint32_t s_wval[FPS_THREADS / 32];
    __shared__ int      s_widx[FPS_THREADS / 32];
    // rslot[parity][src_rank][word]: w0=(tag|val) w1=(tag|x) w2=(tag|y) w3=(tag|z)
    __shared__ unsigned long long rslot[2][FPS_CLUSTER][4];

    uint32_t rank;
    asm("mov.u32 %0, %%cluster_ctarank;" : "=r"(rank));
    int b = blockIdx.x / FPS_CLUSTER;
    int t = threadIdx.x, w = t >> 5, lane = t & 31;
    const float4* pts = g_pts + (size_t)b * NPTS;
    int base = (int)rank * FPS_CHUNK + t * FPS_PPT;

    // init all slot tags to an impossible value before any peer can store
    if (t < 2 * FPS_CLUSTER * 4) {
        ((unsigned long long*)rslot)[t] = ~0ull;
    }

    const uint32_t MD0 = __float_as_uint(1e10f);
    unsigned long long pxp[FPS_PAIRS], pyp[FPS_PAIRS], pzp[FPS_PAIRS];
    uint32_t md[FPS_PPT];
#pragma unroll
    for (int j = 0; j < FPS_PAIRS; j++) {
        float4 p0 = pts[base + 2 * j];
        float4 p1 = pts[base + 2 * j + 1];
        pxp[j] = pack2(p0.x, p1.x);
        pyp[j] = pack2(p0.y, p1.y);
        pzp[j] = pack2(p0.z, p1.z);
        md[2 * j] = MD0;
        md[2 * j + 1] = MD0;
    }

    float4 p00 = pts[0];
    float lx = p00.x, ly = p00.y, lz = p00.z;
    float* cout = g_centers + (size_t)b * NGROUP * 3;
    if (rank == 0 && t == 0) { cout[0] = lx; cout[1] = ly; cout[2] = lz; }

    // one-time cluster barrier: slot init must complete before any peer store
    asm volatile("barrier.cluster.arrive.aligned;" ::: "memory");
    asm volatile("barrier.cluster.wait.aligned;" ::: "memory");

    const int my_rk = lane >> 2;     // rank this lane targets (publish)
    const int my_wd = lane & 3;      // word this lane builds (publish)

    for (int g = 1; g < NGROUP; g++) {
        int p = g & 1;
        unsigned long long tag = ((unsigned long long)(uint32_t)g) << 32;
        unsigned long long nlx2 = pack2(-lx, -lx);
        unsigned long long nly2 = pack2(-ly, -ly);
        unsigned long long nlz2 = pack2(-lz, -lz);
        uint32_t bv = 0; int bk = base;
#pragma unroll
        for (int j = 0; j < FPS_PAIRS; j++) {
            unsigned long long dx2 = addx2(pxp[j], nlx2);
            unsigned long long dy2 = addx2(pyp[j], nly2);
            unsigned long long dz2 = addx2(pzp[j], nlz2);
            unsigned long long dd  = addx2(addx2(mulx2(dx2, dx2), mulx2(dy2, dy2)),
                                           mulx2(dz2, dz2));
            uint32_t d0 = (uint32_t)dd, d1 = (uint32_t)(dd >> 32);
            uint32_t m0 = umin(md[2 * j], d0);
            md[2 * j] = m0;
            if (m0 > bv) { bv = m0; bk = base + 2 * j; }
            uint32_t m1 = umin(md[2 * j + 1], d1);
            md[2 * j + 1] = m1;
            if (m1 > bv) { bv = m1; bk = base + 2 * j + 1; }
        }
        // warp winner: value via redux, index via ballot (lane order == idx order)
        uint32_t wv = __reduce_max_sync(0xFFFFFFFFu, bv);
        uint32_t mm = __ballot_sync(0xFFFFFFFFu, bv == wv);
        int leader = __ffs((int)mm) - 1;
        int wi = __shfl_sync(0xFFFFFFFFu, bk, leader);
        if (lane == 0) { s_wval[w] = wv; s_widx[w] = wi; }
        __syncthreads();

        if (w == 0) {
            // all 32 lanes redundantly scan the 8 warp winners (broadcast LDS);
            // ascending warp order + strict > => smallest idx on value tie
            uint32_t cv = s_wval[0]; int ci = s_widx[0];
#pragma unroll
            for (int i = 1; i < FPS_THREADS / 32; i++)
                if (s_wval[i] > cv) { cv = s_wval[i]; ci = s_widx[i]; }
            float4 cp = pts[ci];     // own chunk -> L1-resident, broadcast addr
            unsigned long long word;
            if      (my_wd == 0) word = tag | cv;
            else if (my_wd == 1) word = tag | __float_as_uint(cp.x);
            else if (my_wd == 2) word = tag | __float_as_uint(cp.y);
            else                 word = tag | __float_as_uint(cp.z);
            uint32_t la = smem_u32(&rslot[p][rank][my_wd]);
            dsm_st(mapa_sh(la, (uint32_t)my_rk), word);   // one store per lane
        }

        // poll all ranks' val words (ALL threads, serial — empirically fastest);
        // ascending rank + strict > => smallest global index on value ties
        uint32_t bestv = 0; int bestr = 0;
#pragma unroll
        for (int r = 0; r < FPS_CLUSTER; r++) {
            uint32_t ap = smem_u32(&rslot[p][r][0]);
            unsigned long long pl;
            do { pl = poll_ld(ap); } while ((uint32_t)(pl >> 32) != (uint32_t)g);
            uint32_t v = (uint32_t)pl;
            if (v > bestv) { bestv = v; bestr = r; }
        }
        // fetch winner coords (each word self-tagged -> no ordering needed)
        {
            uint32_t ab = smem_u32(&rslot[p][bestr][0]);
            unsigned long long w1, w2, w3;
            do { w1 = poll_ld(ab + 8);  } while ((uint32_t)(w1 >> 32) != (uint32_t)g);
            do { w2 = poll_ld(ab + 16); } while ((uint32_t)(w2 >> 32) != (uint32_t)g);
            do { w3 = poll_ld(ab + 24); } while ((uint32_t)(w3 >> 32) != (uint32_t)g);
            lx = __uint_as_float((uint32_t)w1);
            ly = __uint_as_float((uint32_t)w2);
            lz = __uint_as_float((uint32_t)w3);
        }
        if (rank == 0 && t == 0) {
            cout[3 * g] = lx; cout[3 * g + 1] = ly; cout[3 * g + 2] = lz;
        }
    }
}

// ---------------------------------------------------------------------------
// KNN + gather: EXACT R9 code (block-parallel iterative selection — proven
// faster than the warp-0-only variant), with one addition: tail threads also
// write this group's center to the output (folds the centers_out launch).
// ---------------------------------------------------------------------------
__global__ void __launch_bounds__(KT)
knn_kernel(const float* __restrict__ x, float* __restrict__ out_neigh,
           float* __restrict__ out_cen) {
    extern __shared__ uint32_t skey[];          // NPTS ordered keys (64 KB)
    __shared__ uint32_t wk[KT / 32];
    __shared__ uint32_t wi[KT / 32];
    __shared__ uint32_t sel[KNN];
    __shared__ uint32_t s_win;

    int b  = blockIdx.y;
    int gq = blockIdx.x;
    int t = threadIdx.x, w = t >> 5, lane = t & 31;
    const float4* pts = g_pts + (size_t)b * NPTS;
    const float* c3 = g_centers + ((size_t)b * NGROUP + gq) * 3;
    float cx = c3[0], cy = c3[1], cz = c3[2];
    float cc = __fadd_rn(__fadd_rn(__fmul_rn(cx, cx), __fmul_rn(cy, cy)),
                         __fmul_rn(cz, cz));

    uint32_t tk = 0xFFFFFFFFu, ti = 0xFFFFFFFFu;
#pragma unroll
    for (int kk = 0; kk < KPT; kk++) {
        int i = kk * KT + t;
        float4 p = pts[i];
        float dot = __fmaf_rn(cz, p.z, __fmaf_rn(cy, p.y, __fmul_rn(cx, p.x)));
        float d2  = __fsub_rn(__fadd_rn(cc, p.w), __fmul_rn(2.0f, dot));
        uint32_t u = __float_as_uint(d2);
        uint32_t o = u ^ (uint32_t)(((int)u >> 31) | 0x80000000);
        skey[i] = o;
        if (o < tk) { tk = o; ti = (uint32_t)i; }
    }
    {
        uint32_t rk = tk, ri = ti;
#pragma unroll
        for (int off = 16; off > 0; off >>= 1) {
            uint32_t ok = __shfl_down_sync(0xFFFFFFFFu, rk, off);
            uint32_t oi = __shfl_down_sync(0xFFFFFFFFu, ri, off);
            if (ok < rk || (ok == rk && oi < ri)) { rk = ok; ri = oi; }
        }
        if (lane == 0) { wk[w] = rk; wi[w] = ri; }
    }
    __syncthreads();

    for (int j = 0; j < KNN; j++) {
        if (w == 0) {
            uint32_t ak = (lane < KT / 32) ? wk[lane] : 0xFFFFFFFFu;
            uint32_t ai = (lane < KT / 32) ? wi[lane] : 0xFFFFFFFFu;
#pragma unroll
            for (int off = 16; off > 0; off >>= 1) {
                uint32_t ok = __shfl_down_sync(0xFFFFFFFFu, ak, off);
                uint32_t oi = __shfl_down_sync(0xFFFFFFFFu, ai, off);
                if (ok < ak || (ok == ak && oi < ai)) { ak = ok; ai = oi; }
            }
            if (lane == 0) { sel[j] = ai; s_win = ai; }
        }
        __syncthreads();
        uint32_t widx = s_win;
        int owner = (int)(widx & (KT - 1));
        if (t == owner) {
            skey[widx] = 0xFFFFFFFFu;
            tk = 0xFFFFFFFFu; ti = 0xFFFFFFFFu;
#pragma unroll
            for (int kk = 0; kk < KPT; kk++) {
                int i = kk * KT + t;
                uint32_t o = skey[i];
                if (o < tk) { tk = o; ti = (uint32_t)i; }
            }
        }
        if (w == (owner >> 5)) {
            uint32_t rk = tk, ri = ti;
#pragma unroll
            for (int off = 16; off > 0; off >>= 1) {
                uint32_t ok = __shfl_down_sync(0xFFFFFFFFu, rk, off);
                uint32_t oi = __shfl_down_sync(0xFFFFFFFFu, ri, off);
                if (ok < rk || (ok == rk && oi < ri)) { rk = ok; ri = oi; }
            }
            if (lane == 0) { wk[w] = rk; wi[w] = ri; }
        }
        __syncthreads();
    }

    if (t < KNN * CH) {
        int jj = t / CH, c = t % CH;
        uint32_t idx = sel[jj];
        float v = x[((size_t)b * NPTS + idx) * CH + c];
        if (c >= 4 && c < 7) {
            float cv = (c == 4) ? cx : ((c == 5) ? cy : cz);
            v = __fadd_rn(v, -cv);
        }
        out_neigh[(((size_t)b * NGROUP + gq) * KNN + jj) * CH + c] = v;
    } else if (t >= KNN * CH && t < KNN * CH + 3 && out_cen != nullptr) {
        int c = t - KNN * CH;
        out_cen[((size_t)b * NGROUP + gq) * 3 + c] = c3[c];
    }
}

extern "C" void kernel_launch(void* const* d_in, const int* in_sizes, int n_in,
                              void* d_out, int out_size) {
    const float* x = (const float*)d_in[0];
    float* out = (float*)d_out;
    float* out_cen = ((size_t)out_size >= NEIGH_ELEMS + CEN_ELEMS)
                         ? (out + NEIGH_ELEMS) : nullptr;

    cudaFuncSetAttribute(knn_kernel, cudaFuncAttributeMaxDynamicSharedMemorySize,
                         NPTS * sizeof(uint32_t));

    prep_kernel<<<(BATCH * NPTS + 255) / 256, 256>>>(x);
    fps_kernel<<<BATCH * FPS_CLUSTER, FPS_THREADS>>>();
    knn_kernel<<<dim3(NGROUP, BATCH), KT, NPTS * sizeof(uint32_t)>>>(x, out, out_cen);
}

// round 14
// speedup vs baseline: 1.7882x; 1.0119x over previous
#include <cuda_runtime.h>
#include <cstdint>

#define BATCH   8
#define NPTS    16384
#define CH      13
#define NGROUP  512
#define KNN     32

#define FPS_CLUSTER 4
#define FPS_THREADS 256
#define FPS_CHUNK   (NPTS / FPS_CLUSTER)            // 4096 points per CTA
#define FPS_PPT     (FPS_CHUNK / FPS_THREADS)       // 16 points per thread
#define FPS_PAIRS   (FPS_PPT / 2)                   // 8 packed pairs

#define KT      512                 // knn threads per block
#define KPT     (NPTS / KT)         // 32 points per thread

#define NEIGH_ELEMS ((size_t)BATCH * NGROUP * KNN * CH)  // 1,703,936
#define CEN_ELEMS   ((size_t)BATCH * NGROUP * 3)         // 12,288

// Static device scratch (no allocation allowed).
__device__ float4 g_pts[BATCH * NPTS];          // x,y,z,pp  (2 MB)
__device__ float  g_centers[BATCH * NGROUP * 3];

// ---------------------------------------------------------------------------
// Prep: pack xyz (channels 4:7) + pp = ((x^2+y^2)+z^2) (non-FMA, XLA order)
// ---------------------------------------------------------------------------
__global__ void prep_kernel(const float* __restrict__ x) {
    int i = blockIdx.x * blockDim.x + threadIdx.x;
    if (i >= BATCH * NPTS) return;
    const float* p = x + (size_t)i * CH;
    float px = p[4], py = p[5], pz = p[6];
    float pp = __fadd_rn(__fadd_rn(__fmul_rn(px, px), __fmul_rn(py, py)),
                         __fmul_rn(pz, pz));
    g_pts[i] = make_float4(px, py, pz, pp);
}

__device__ __forceinline__ uint32_t smem_u32(const void* p) {
    return (uint32_t)__cvta_generic_to_shared(p);
}
__device__ __forceinline__ unsigned long long pack2(float a, float b) {
    unsigned long long r;
    asm("mov.b64 %0, {%1, %2};" : "=l"(r) : "f"(a), "f"(b));
    return r;
}
__device__ __forceinline__ unsigned long long addx2(unsigned long long a,
                                                    unsigned long long b) {
    unsigned long long r;
    asm("add.rn.f32x2 %0, %1, %2;" : "=l"(r) : "l"(a), "l"(b));
    return r;
}
__device__ __forceinline__ unsigned long long mulx2(unsigned long long a,
                                                    unsigned long long b) {
    unsigned long long r;
    asm("mul.rn.f32x2 %0, %1, %2;" : "=l"(r) : "l"(a), "l"(b));
    return r;
}
__device__ __forceinline__ uint32_t mapa_sh(uint32_t addr, uint32_t r) {
    uint32_t o;
    asm("mapa.shared::cluster.u32 %0, %1, %2;" : "=r"(o) : "r"(addr), "r"(r));
    return o;
}
__device__ __forceinline__ void dsm_st(uint32_t addr, unsigned long long v) {
    asm volatile("st.relaxed.cluster.shared::cluster.u64 [%0], %1;"
                 :: "r"(addr), "l"(v) : "memory");
}
__device__ __forceinline__ unsigned long long poll_ld(uint32_t addr) {
    unsigned long long v;
    asm volatile("ld.relaxed.cluster.shared::cta.u64 %0, [%1];"
                 : "=l"(v) : "r"(addr) : "memory");
    return v;
}

// ---------------------------------------------------------------------------
// FPS: R9 protocol FROZEN (single __syncthreads/iter, self-tagged double-
// buffered 4-word DSMEM slots, warp-0 lane-parallel publish, serial
// per-thread poll, no trailing barrier). One-parameter experiment this
// round: FPS_CLUSTER 8 -> 4 (bigger per-CTA update, but half the rank skew,
// half the poll chain, quarter the DSMEM words in flight).
// All tie-breaks ascending-index at every level => identical to jnp.argmax.
// ---------------------------------------------------------------------------
__global__ void __cluster_dims__(FPS_CLUSTER, 1, 1) __launch_bounds__(FPS_THREADS, 1)
fps_kernel() {
    __shared__ uint32_t s_wval[FPS_THREADS / 32];
    __shared__ int      s_widx[FPS_THREADS / 32];
    // rslot[parity][src_rank][word]: w0=(tag|val) w1=(tag|x) w2=(tag|y) w3=(tag|z)
    __shared__ unsigned long long rslot[2][FPS_CLUSTER][4];

    uint32_t rank;
    asm("mov.u32 %0, %%cluster_ctarank;" : "=r"(rank));
    int b = blockIdx.x / FPS_CLUSTER;
    int t = threadIdx.x, w = t >> 5, lane = t & 31;
    const float4* pts = g_pts + (size_t)b * NPTS;
    int base = (int)rank * FPS_CHUNK + t * FPS_PPT;

    // init all slot tags to an impossible value before any peer can store
    if (t < 2 * FPS_CLUSTER * 4) {
        ((unsigned long long*)rslot)[t] = ~0ull;
    }

    const uint32_t MD0 = __float_as_uint(1e10f);
    unsigned long long pxp[FPS_PAIRS], pyp[FPS_PAIRS], pzp[FPS_PAIRS];
    uint32_t md[FPS_PPT];
#pragma unroll
    for (int j = 0; j < FPS_PAIRS; j++) {
        float4 p0 = pts[base + 2 * j];
        float4 p1 = pts[base + 2 * j + 1];
        pxp[j] = pack2(p0.x, p1.x);
        pyp[j] = pack2(p0.y, p1.y);
        pzp[j] = pack2(p0.z, p1.z);
        md[2 * j] = MD0;
        md[2 * j + 1] = MD0;
    }

    float4 p00 = pts[0];
    float lx = p00.x, ly = p00.y, lz = p00.z;
    float* cout = g_centers + (size_t)b * NGROUP * 3;
    if (rank == 0 && t == 0) { cout[0] = lx; cout[1] = ly; cout[2] = lz; }

    // one-time cluster barrier: slot init must complete before any peer store
    asm volatile("barrier.cluster.arrive.aligned;" ::: "memory");
    asm volatile("barrier.cluster.wait.aligned;" ::: "memory");

    const int my_rk = lane >> 2;     // rank this lane targets (publish)
    const int my_wd = lane & 3;      // word this lane builds (publish)

    for (int g = 1; g < NGROUP; g++) {
        int p = g & 1;
        unsigned long long tag = ((unsigned long long)(uint32_t)g) << 32;
        unsigned long long nlx2 = pack2(-lx, -lx);
        unsigned long long nly2 = pack2(-ly, -ly);
        unsigned long long nlz2 = pack2(-lz, -lz);
        uint32_t bv = 0; int bk = base;
#pragma unroll
        for (int j = 0; j < FPS_PAIRS; j++) {
            unsigned long long dx2 = addx2(pxp[j], nlx2);
            unsigned long long dy2 = addx2(pyp[j], nly2);
            unsigned long long dz2 = addx2(pzp[j], nlz2);
            unsigned long long dd  = addx2(addx2(mulx2(dx2, dx2), mulx2(dy2, dy2)),
                                           mulx2(dz2, dz2));
            uint32_t d0 = (uint32_t)dd, d1 = (uint32_t)(dd >> 32);
            uint32_t m0 = umin(md[2 * j], d0);
            md[2 * j] = m0;
            if (m0 > bv) { bv = m0; bk = base + 2 * j; }
            uint32_t m1 = umin(md[2 * j + 1], d1);
            md[2 * j + 1] = m1;
            if (m1 > bv) { bv = m1; bk = base + 2 * j + 1; }
        }
        // warp winner: value via redux, index via ballot (lane order == idx order)
        uint32_t wv = __reduce_max_sync(0xFFFFFFFFu, bv);
        uint32_t mm = __ballot_sync(0xFFFFFFFFu, bv == wv);
        int leader = __ffs((int)mm) - 1;
        int wi = __shfl_sync(0xFFFFFFFFu, bk, leader);
        if (lane == 0) { s_wval[w] = wv; s_widx[w] = wi; }
        __syncthreads();

        if (w == 0) {
            // all 32 lanes redundantly scan the 8 warp winners (broadcast LDS);
            // ascending warp order + strict > => smallest idx on value tie
            uint32_t cv = s_wval[0]; int ci = s_widx[0];
#pragma unroll
            for (int i = 1; i < FPS_THREADS / 32; i++)
                if (s_wval[i] > cv) { cv = s_wval[i]; ci = s_widx[i]; }
            float4 cp = pts[ci];     // own chunk -> L1-resident, broadcast addr
            unsigned long long word;
            if      (my_wd == 0) word = tag | cv;
            else if (my_wd == 1) word = tag | __float_as_uint(cp.x);
            else if (my_wd == 2) word = tag | __float_as_uint(cp.y);
            else                 word = tag | __float_as_uint(cp.z);
            if (lane < 4 * FPS_CLUSTER) {
                uint32_t la = smem_u32(&rslot[p][rank][my_wd]);
                dsm_st(mapa_sh(la, (uint32_t)my_rk), word);  // one store per lane
            }
        }

        // poll all ranks' val words (ALL threads, serial — empirically fastest);
        // ascending rank + strict > => smallest global index on value ties
        uint32_t bestv = 0; int bestr = 0;
#pragma unroll
        for (int r = 0; r < FPS_CLUSTER; r++) {
            uint32_t ap = smem_u32(&rslot[p][r][0]);
            unsigned long long pl;
            do { pl = poll_ld(ap); } while ((uint32_t)(pl >> 32) != (uint32_t)g);
            uint32_t v = (uint32_t)pl;
            if (v > bestv) { bestv = v; bestr = r; }
        }
        // fetch winner coords (each word self-tagged -> no ordering needed)
        {
            uint32_t ab = smem_u32(&rslot[p][bestr][0]);
            unsigned long long w1, w2, w3;
            do { w1 = poll_ld(ab + 8);  } while ((uint32_t)(w1 >> 32) != (uint32_t)g);
            do { w2 = poll_ld(ab + 16); } while ((uint32_t)(w2 >> 32) != (uint32_t)g);
            do { w3 = poll_ld(ab + 24); } while ((uint32_t)(w3 >> 32) != (uint32_t)g);
            lx = __uint_as_float((uint32_t)w1);
            ly = __uint_as_float((uint32_t)w2);
            lz = __uint_as_float((uint32_t)w3);
        }
        if (rank == 0 && t == 0) {
            cout[3 * g] = lx; cout[3 * g + 1] = ly; cout[3 * g + 2] = lz;
        }
    }
}

// ---------------------------------------------------------------------------
// KNN + gather: EXACT R9/R13 code (block-parallel iterative selection),
// with centers folded into the output tail.
// ---------------------------------------------------------------------------
__global__ void __launch_bounds__(KT)
knn_kernel(const float* __restrict__ x, float* __restrict__ out_neigh,
           float* __restrict__ out_cen) {
    extern __shared__ uint32_t skey[];          // NPTS ordered keys (64 KB)
    __shared__ uint32_t wk[KT / 32];
    __shared__ uint32_t wi[KT / 32];
    __shared__ uint32_t sel[KNN];
    __shared__ uint32_t s_win;

    int b  = blockIdx.y;
    int gq = blockIdx.x;
    int t = threadIdx.x, w = t >> 5, lane = t & 31;
    const float4* pts = g_pts + (size_t)b * NPTS;
    const float* c3 = g_centers + ((size_t)b * NGROUP + gq) * 3;
    float cx = c3[0], cy = c3[1], cz = c3[2];
    float cc = __fadd_rn(__fadd_rn(__fmul_rn(cx, cx), __fmul_rn(cy, cy)),
                         __fmul_rn(cz, cz));

    uint32_t tk = 0xFFFFFFFFu, ti = 0xFFFFFFFFu;
#pragma unroll
    for (int kk = 0; kk < KPT; kk++) {
        int i = kk * KT + t;
        float4 p = pts[i];
        float dot = __fmaf_rn(cz, p.z, __fmaf_rn(cy, p.y, __fmul_rn(cx, p.x)));
        float d2  = __fsub_rn(__fadd_rn(cc, p.w), __fmul_rn(2.0f, dot));
        uint32_t u = __float_as_uint(d2);
        uint32_t o = u ^ (uint32_t)(((int)u >> 31) | 0x80000000);
        skey[i] = o;
        if (o < tk) { tk = o; ti = (uint32_t)i; }
    }
    {
        uint32_t rk = tk, ri = ti;
#pragma unroll
        for (int off = 16; off > 0; off >>= 1) {
            uint32_t ok = __shfl_down_sync(0xFFFFFFFFu, rk, off);
            uint32_t oi = __shfl_down_sync(0xFFFFFFFFu, ri, off);
            if (ok < rk || (ok == rk && oi < ri)) { rk = ok; ri = oi; }
        }
        if (lane == 0) { wk[w] = rk; wi[w] = ri; }
    }
    __syncthreads();

    for (int j = 0; j < KNN; j++) {
        if (w == 0) {
            uint32_t ak = (lane < KT / 32) ? wk[lane] : 0xFFFFFFFFu;
            uint32_t ai = (lane < KT / 32) ? wi[lane] : 0xFFFFFFFFu;
#pragma unroll
            for (int off = 16; off > 0; off >>= 1) {
                uint32_t ok = __shfl_down_sync(0xFFFFFFFFu, ak, off);
                uint32_t oi = __shfl_down_sync(0xFFFFFFFFu, ai, off);
                if (ok < ak || (ok == ak && oi < ai)) { ak = ok; ai = oi; }
            }
            if (lane == 0) { sel[j] = ai; s_win = ai; }
        }
        __syncthreads();
        uint32_t widx = s_win;
        int owner = (int)(widx & (KT - 1));
        if (t == owner) {
            skey[widx] = 0xFFFFFFFFu;
            tk = 0xFFFFFFFFu; ti = 0xFFFFFFFFu;
#pragma unroll
            for (int kk = 0; kk < KPT; kk++) {
                int i = kk * KT + t;
                uint32_t o = skey[i];
                if (o < tk) { tk = o; ti = (uint32_t)i; }
            }
        }
        if (w == (owner >> 5)) {
            uint32_t rk = tk, ri = ti;
#pragma unroll
            for (int off = 16; off > 0; off >>= 1) {
                uint32_t ok = __shfl_down_sync(0xFFFFFFFFu, rk, off);
                uint32_t oi = __shfl_down_sync(0xFFFFFFFFu, ri, off);
                if (ok < rk || (ok == rk && oi < ri)) { rk = ok; ri = oi; }
            }
            if (lane == 0) { wk[w] = rk; wi[w] = ri; }
        }
        __syncthreads();
    }

    if (t < KNN * CH) {
        int jj = t / CH, c = t % CH;
        uint32_t idx = sel[jj];
        float v = x[((size_t)b * NPTS + idx) * CH + c];
        if (c >= 4 && c < 7) {
            float cv = (c == 4) ? cx : ((c == 5) ? cy : cz);
            v = __fadd_rn(v, -cv);
        }
        out_neigh[(((size_t)b * NGROUP + gq) * KNN + jj) * CH + c] = v;
    } else if (t >= KNN * CH && t < KNN * CH + 3 && out_cen != nullptr) {
        int c = t - KNN * CH;
        out_cen[((size_t)b * NGROUP + gq) * 3 + c] = c3[c];
    }
}

extern "C" void kernel_launch(void* const* d_in, const int* in_sizes, int n_in,
                              void* d_out, int out_size) {
    const float* x = (const float*)d_in[0];
    float* out = (float*)d_out;
    float* out_cen = ((size_t)out_size >= NEIGH_ELEMS + CEN_ELEMS)
                         ? (out + NEIGH_ELEMS) : nullptr;

    cudaFuncSetAttribute(knn_kernel, cudaFuncAttributeMaxDynamicSharedMemorySize,
                         NPTS * sizeof(uint32_t));

    prep_kernel<<<(BATCH * NPTS + 255) / 256, 256>>>(x);
    fps_kernel<<<BATCH * FPS_CLUSTER, FPS_THREADS>>>();
    knn_kernel<<<dim3(NGROUP, BATCH), KT, NPTS * sizeof(uint32_t)>>>(x, out, out_cen);
}

// round 15
// speedup vs baseline: 2.1446x; 1.1994x over previous
#include <cuda_runtime.h>
#include <cstdint>

#define BATCH   8
#define NPTS    16384
#define CH      13
#define NGROUP  512
#define KNN     32

#define FPS_CLUSTER 4
#define FT      512                               // fused block threads
#define FPS_CHUNK   (NPTS / FPS_CLUSTER)          // 4096 points per CTA
#define FPS_PPT     (FPS_CHUNK / FT)              // 8 points per thread
#define FPS_PAIRS   (FPS_PPT / 2)                 // 4 packed pairs
#define NFPSBLK     (BATCH * FPS_CLUSTER)         // 32

#define KPT     (NPTS / FT)         // 32 points per thread

#define NEIGH_ELEMS ((size_t)BATCH * NGROUP * KNN * CH)  // 1,703,936
#define CEN_ELEMS   ((size_t)BATCH * NGROUP * 3)         // 12,288

// Static device scratch (no allocation allowed).
__device__ float4 g_pts[BATCH * NPTS];          // x,y,z,pp  (2 MB)
__device__ float  g_centers[BATCH * NGROUP * 3];
__device__ int    g_prog[BATCH];                // centers produced per batch

// ---------------------------------------------------------------------------
// Prep: pack xyz + pp = ((x^2+y^2)+z^2) (non-FMA, XLA order); reset progress.
// ---------------------------------------------------------------------------
__global__ void prep_kernel(const float* __restrict__ x) {
    int i = blockIdx.x * blockDim.x + threadIdx.x;
    if (i < BATCH) g_prog[i] = 0;
    if (i >= BATCH * NPTS) return;
    const float* p = x + (size_t)i * CH;
    float px = p[4], py = p[5], pz = p[6];
    float pp = __fadd_rn(__fadd_rn(__fmul_rn(px, px), __fmul_rn(py, py)),
                         __fmul_rn(pz, pz));
    g_pts[i] = make_float4(px, py, pz, pp);
}

__device__ __forceinline__ uint32_t smem_u32(const void* p) {
    return (uint32_t)__cvta_generic_to_shared(p);
}
__device__ __forceinline__ unsigned long long pack2(float a, float b) {
    unsigned long long r;
    asm("mov.b64 %0, {%1, %2};" : "=l"(r) : "f"(a), "f"(b));
    return r;
}
__device__ __forceinline__ unsigned long long addx2(unsigned long long a,
                                                    unsigned long long b) {
    unsigned long long r;
    asm("add.rn.f32x2 %0, %1, %2;" : "=l"(r) : "l"(a), "l"(b));
    return r;
}
__device__ __forceinline__ unsigned long long mulx2(unsigned long long a,
                                                    unsigned long long b) {
    unsigned long long r;
    asm("mul.rn.f32x2 %0, %1, %2;" : "=l"(r) : "l"(a), "l"(b));
    return r;
}
__device__ __forceinline__ uint32_t mapa_sh(uint32_t addr, uint32_t r) {
    uint32_t o;
    asm("mapa.shared::cluster.u32 %0, %1, %2;" : "=r"(o) : "r"(addr), "r"(r));
    return o;
}
__device__ __forceinline__ void dsm_st(uint32_t addr, unsigned long long v) {
    asm volatile("st.relaxed.cluster.shared::cluster.u64 [%0], %1;"
                 :: "r"(addr), "l"(v) : "memory");
}
__device__ __forceinline__ unsigned long long poll_ld(uint32_t addr) {
    unsigned long long v;
    asm volatile("ld.relaxed.cluster.shared::cta.u64 %0, [%1];"
                 : "=l"(v) : "r"(addr) : "memory");
    return v;
}

// ---------------------------------------------------------------------------
// Fused kernel. Blocks [0,32): FPS (frozen R14 protocol @512 threads).
// Blocks [32, 32+4096): KNN for (b = kidx&7, gq = kidx>>3), gated on a
// per-batch release/acquire progress counter so KNN overlaps FPS.
// Role boundary 32 is divisible by FPS_CLUSTER => every cluster homogeneous.
// ---------------------------------------------------------------------------
__global__ void __cluster_dims__(FPS_CLUSTER, 1, 1) __launch_bounds__(FT, 2)
fused_kernel(const float* __restrict__ x, float* __restrict__ out_neigh,
             float* __restrict__ out_cen) {
    extern __shared__ uint32_t skey[];          // KNN: NPTS keys (64 KB)
    __shared__ uint32_t s_wval[FT / 32];
    __shared__ int      s_widx[FT / 32];
    __shared__ uint32_t sel[KNN];
    __shared__ uint32_t s_win;
    __shared__ unsigned long long rslot[2][FPS_CLUSTER][4];

    int bx = blockIdx.x;
    int t = threadIdx.x, w = t >> 5, lane = t & 31;

    if (bx < NFPSBLK) {
        // =================== FPS role (frozen R14 protocol) ===================
        uint32_t rank;
        asm("mov.u32 %0, %%cluster_ctarank;" : "=r"(rank));
        int b = bx / FPS_CLUSTER;
        const float4* pts = g_pts + (size_t)b * NPTS;
        int base = (int)rank * FPS_CHUNK + t * FPS_PPT;

        if (t < 2 * FPS_CLUSTER * 4) ((unsigned long long*)rslot)[t] = ~0ull;

        const uint32_t MD0 = __float_as_uint(1e10f);
        unsigned long long pxp[FPS_PAIRS], pyp[FPS_PAIRS], pzp[FPS_PAIRS];
        uint32_t md[FPS_PPT];
#pragma unroll
        for (int j = 0; j < FPS_PAIRS; j++) {
            float4 p0 = pts[base + 2 * j];
            float4 p1 = pts[base + 2 * j + 1];
            pxp[j] = pack2(p0.x, p1.x);
            pyp[j] = pack2(p0.y, p1.y);
            pzp[j] = pack2(p0.z, p1.z);
            md[2 * j] = MD0;
            md[2 * j + 1] = MD0;
        }

        float4 p00 = pts[0];
        float lx = p00.x, ly = p00.y, lz = p00.z;
        float* cout = g_centers + (size_t)b * NGROUP * 3;
        if (rank == 0 && t == 0) {
            cout[0] = lx; cout[1] = ly; cout[2] = lz;
            int one = 1;
            asm volatile("st.release.gpu.b32 [%0], %1;"
                         :: "l"(&g_prog[b]), "r"(one) : "memory");
        }

        asm volatile("barrier.cluster.arrive.aligned;" ::: "memory");
        asm volatile("barrier.cluster.wait.aligned;" ::: "memory");

        const int my_rk = lane >> 2;
        const int my_wd = lane & 3;

        for (int g = 1; g < NGROUP; g++) {
            int p = g & 1;
            unsigned long long tag = ((unsigned long long)(uint32_t)g) << 32;
            unsigned long long nlx2 = pack2(-lx, -lx);
            unsigned long long nly2 = pack2(-ly, -ly);
            unsigned long long nlz2 = pack2(-lz, -lz);
            uint32_t bv = 0; int bk = base;
#pragma unroll
            for (int j = 0; j < FPS_PAIRS; j++) {
                unsigned long long dx2 = addx2(pxp[j], nlx2);
                unsigned long long dy2 = addx2(pyp[j], nly2);
                unsigned long long dz2 = addx2(pzp[j], nlz2);
                unsigned long long dd  = addx2(addx2(mulx2(dx2, dx2), mulx2(dy2, dy2)),
                                               mulx2(dz2, dz2));
                uint32_t d0 = (uint32_t)dd, d1 = (uint32_t)(dd >> 32);
                uint32_t m0 = umin(md[2 * j], d0);
                md[2 * j] = m0;
                if (m0 > bv) { bv = m0; bk = base + 2 * j; }
                uint32_t m1 = umin(md[2 * j + 1], d1);
                md[2 * j + 1] = m1;
                if (m1 > bv) { bv = m1; bk = base + 2 * j + 1; }
            }
            uint32_t wv = __reduce_max_sync(0xFFFFFFFFu, bv);
            uint32_t mm = __ballot_sync(0xFFFFFFFFu, bv == wv);
            int leader = __ffs((int)mm) - 1;
            int wi = __shfl_sync(0xFFFFFFFFu, bk, leader);
            if (lane == 0) { s_wval[w] = wv; s_widx[w] = wi; }
            __syncthreads();

            if (w == 0) {
                // scan 16 warp winners, ascending warp order (== index order)
                uint32_t cv = s_wval[0]; int ci = s_widx[0];
#pragma unroll
                for (int i = 1; i < FT / 32; i++)
                    if (s_wval[i] > cv) { cv = s_wval[i]; ci = s_widx[i]; }
                float4 cp = pts[ci];
                unsigned long long word;
                if      (my_wd == 0) word = tag | cv;
                else if (my_wd == 1) word = tag | __float_as_uint(cp.x);
                else if (my_wd == 2) word = tag | __float_as_uint(cp.y);
                else                 word = tag | __float_as_uint(cp.z);
                if (lane < 4 * FPS_CLUSTER) {
                    uint32_t la = smem_u32(&rslot[p][rank][my_wd]);
                    dsm_st(mapa_sh(la, (uint32_t)my_rk), word);
                }
            }

            // serial per-thread poll (empirically fastest)
            uint32_t bestv = 0; int bestr = 0;
#pragma unroll
            for (int r = 0; r < FPS_CLUSTER; r++) {
                uint32_t ap = smem_u32(&rslot[p][r][0]);
                unsigned long long pl;
                do { pl = poll_ld(ap); } while ((uint32_t)(pl >> 32) != (uint32_t)g);
                uint32_t v = (uint32_t)pl;
                if (v > bestv) { bestv = v; bestr = r; }
            }
            {
                uint32_t ab = smem_u32(&rslot[p][bestr][0]);
                unsigned long long w1, w2, w3;
                do { w1 = poll_ld(ab + 8);  } while ((uint32_t)(w1 >> 32) != (uint32_t)g);
                do { w2 = poll_ld(ab + 16); } while ((uint32_t)(w2 >> 32) != (uint32_t)g);
                do { w3 = poll_ld(ab + 24); } while ((uint32_t)(w3 >> 32) != (uint32_t)g);
                lx = __uint_as_float((uint32_t)w1);
                ly = __uint_as_float((uint32_t)w2);
                lz = __uint_as_float((uint32_t)w3);
            }
            if (rank == 0 && t == 0) {
                cout[3 * g] = lx; cout[3 * g + 1] = ly; cout[3 * g + 2] = lz;
                int gp = g + 1;
                asm volatile("st.release.gpu.b32 [%0], %1;"
                             :: "l"(&g_prog[b]), "r"(gp) : "memory");
            }
        }
        return;
    }

    // ====================== KNN role (byte-identical R14 body) ==============
    int kidx = bx - NFPSBLK;
    int b  = kidx & (BATCH - 1);
    int gq = kidx >> 3;

    // gate: wait until center gq for batch b has been published
    if (t == 0) {
        for (;;) {
            int v;
            asm volatile("ld.acquire.gpu.b32 %0, [%1];"
                         : "=r"(v) : "l"(&g_prog[b]) : "memory");
            if (v > gq) break;
            __nanosleep(256);
        }
    }
    __syncthreads();

    const float4* pts = g_pts + (size_t)b * NPTS;
    const float* c3 = g_centers + ((size_t)b * NGROUP + gq) * 3;
    float cx = c3[0], cy = c3[1], cz = c3[2];
    float cc = __fadd_rn(__fadd_rn(__fmul_rn(cx, cx), __fmul_rn(cy, cy)),
                         __fmul_rn(cz, cz));

    uint32_t tk = 0xFFFFFFFFu, ti = 0xFFFFFFFFu;
#pragma unroll
    for (int kk = 0; kk < KPT; kk++) {
        int i = kk * FT + t;
        float4 p = pts[i];
        float dot = __fmaf_rn(cz, p.z, __fmaf_rn(cy, p.y, __fmul_rn(cx, p.x)));
        float d2  = __fsub_rn(__fadd_rn(cc, p.w), __fmul_rn(2.0f, dot));
        uint32_t u = __float_as_uint(d2);
        uint32_t o = u ^ (uint32_t)(((int)u >> 31) | 0x80000000);
        skey[i] = o;
        if (o < tk) { tk = o; ti = (uint32_t)i; }
    }
    {
        uint32_t rk = tk, ri = ti;
#pragma unroll
        for (int off = 16; off > 0; off >>= 1) {
            uint32_t ok = __shfl_down_sync(0xFFFFFFFFu, rk, off);
            uint32_t oi = __shfl_down_sync(0xFFFFFFFFu, ri, off);
            if (ok < rk || (ok == rk && oi < ri)) { rk = ok; ri = oi; }
        }
        if (lane == 0) { s_wval[w] = rk; s_widx[w] = (int)ri; }
    }
    __syncthreads();

    for (int j = 0; j < KNN; j++) {
        if (w == 0) {
            uint32_t ak = (lane < FT / 32) ? s_wval[lane] : 0xFFFFFFFFu;
            uint32_t ai = (lane < FT / 32) ? (uint32_t)s_widx[lane] : 0xFFFFFFFFu;
#pragma unroll
            for (int off = 16; off > 0; off >>= 1) {
                uint32_t ok = __shfl_down_sync(0xFFFFFFFFu, ak, off);
                uint32_t oi = __shfl_down_sync(0xFFFFFFFFu, ai, off);
                if (ok < ak || (ok == ak && oi < ai)) { ak = ok; ai = oi; }
            }
            if (lane == 0) { sel[j] = ai; s_win = ai; }
        }
        __syncthreads();
        uint32_t widx = s_win;
        int owner = (int)(widx & (FT - 1));
        if (t == owner) {
            skey[widx] = 0xFFFFFFFFu;
            tk = 0xFFFFFFFFu; ti = 0xFFFFFFFFu;
#pragma unroll
            for (int kk = 0; kk < KPT; kk++) {
                int i = kk * FT + t;
                uint32_t o = skey[i];
                if (o < tk) { tk = o; ti = (uint32_t)i; }
            }
        }
        if (w == (owner >> 5)) {
            uint32_t rk = tk, ri = ti;
#pragma unroll
            for (int off = 16; off > 0; off >>= 1) {
                uint32_t ok = __shfl_down_sync(0xFFFFFFFFu, rk, off);
                uint32_t oi = __shfl_down_sync(0xFFFFFFFFu, ri, off);
                if (ok < rk || (ok == rk && oi < ri)) { rk = ok; ri = oi; }
            }
            if (lane == 0) { s_wval[w] = rk; s_widx[w] = (int)ri; }
        }
        __syncthreads();
    }

    if (t < KNN * CH) {
        int jj = t / CH, c = t % CH;
        uint32_t idx = sel[jj];
        float v = x[((size_t)b * NPTS + idx) * CH + c];
        if (c >= 4 && c < 7) {
            float cv = (c == 4) ? cx : ((c == 5) ? cy : cz);
            v = __fadd_rn(v, -cv);
        }
        out_neigh[(((size_t)b * NGROUP + gq) * KNN + jj) * CH + c] = v;
    } else if (t >= KNN * CH && t < KNN * CH + 3 && out_cen != nullptr) {
        int c = t - KNN * CH;
        out_cen[((size_t)b * NGROUP + gq) * 3 + c] = c3[c];
    }
}

extern "C" void kernel_launch(void* const* d_in, const int* in_sizes, int n_in,
                              void* d_out, int out_size) {
    const float* x = (const float*)d_in[0];
    float* out = (float*)d_out;
    float* out_cen = ((size_t)out_size >= NEIGH_ELEMS + CEN_ELEMS)
                         ? (out + NEIGH_ELEMS) : nullptr;

    cudaFuncSetAttribute(fused_kernel, cudaFuncAttributeMaxDynamicSharedMemorySize,
                         NPTS * sizeof(uint32_t));

    prep_kernel<<<(BATCH * NPTS + 255) / 256, 256>>>(x);
    fused_kernel<<<NFPSBLK + BATCH * NGROUP, FT, NPTS * sizeof(uint32_t)>>>(
        x, out, out_cen);
}

// round 16
// speedup vs baseline: 2.1608x; 1.0075x over previous
#include <cuda_runtime.h>
#include <cstdint>

#define BATCH   8
#define NPTS    16384
#define CH      13
#define NGROUP  512
#define KNN     32

#define FPS_CLUSTER 4
#define FT      512                               // fused block threads
#define FPS_CHUNK   (NPTS / FPS_CLUSTER)          // 4096 points per CTA
#define FPS_PPT     (FPS_CHUNK / FT)              // 8 points per thread
#define FPS_PAIRS   (FPS_PPT / 2)                 // 4 packed pairs
#define NFPSBLK     (BATCH * FPS_CLUSTER)         // 32

#define KPT     (NPTS / FT)         // 32 points per thread

#define NEIGH_ELEMS ((size_t)BATCH * NGROUP * KNN * CH)  // 1,703,936
#define CEN_ELEMS   ((size_t)BATCH * NGROUP * 3)         // 12,288

// Static device scratch (no allocation allowed).
__device__ float4 g_pts[BATCH * NPTS];          // x,y,z,pp  (2 MB)
__device__ float  g_centers[BATCH * NGROUP * 3];
__device__ int    g_prog[BATCH];                // centers produced per batch

// ---------------------------------------------------------------------------
// Prep: pack xyz + pp = ((x^2+y^2)+z^2) (non-FMA, XLA order); reset progress.
// ---------------------------------------------------------------------------
__global__ void prep_kernel(const float* __restrict__ x) {
    int i = blockIdx.x * blockDim.x + threadIdx.x;
    if (i < BATCH) g_prog[i] = 0;
    if (i >= BATCH * NPTS) return;
    const float* p = x + (size_t)i * CH;
    float px = p[4], py = p[5], pz = p[6];
    float pp = __fadd_rn(__fadd_rn(__fmul_rn(px, px), __fmul_rn(py, py)),
                         __fmul_rn(pz, pz));
    g_pts[i] = make_float4(px, py, pz, pp);
}

__device__ __forceinline__ uint32_t smem_u32(const void* p) {
    return (uint32_t)__cvta_generic_to_shared(p);
}
__device__ __forceinline__ unsigned long long pack2(float a, float b) {
    unsigned long long r;
    asm("mov.b64 %0, {%1, %2};" : "=l"(r) : "f"(a), "f"(b));
    return r;
}
__device__ __forceinline__ unsigned long long addx2(unsigned long long a,
                                                    unsigned long long b) {
    unsigned long long r;
    asm("add.rn.f32x2 %0, %1, %2;" : "=l"(r) : "l"(a), "l"(b));
    return r;
}
__device__ __forceinline__ unsigned long long mulx2(unsigned long long a,
                                                    unsigned long long b) {
    unsigned long long r;
    asm("mul.rn.f32x2 %0, %1, %2;" : "=l"(r) : "l"(a), "l"(b));
    return r;
}
__device__ __forceinline__ uint32_t mapa_sh(uint32_t addr, uint32_t r) {
    uint32_t o;
    asm("mapa.shared::cluster.u32 %0, %1, %2;" : "=r"(o) : "r"(addr), "r"(r));
    return o;
}
__device__ __forceinline__ void dsm_st(uint32_t addr, unsigned long long v) {
    asm volatile("st.relaxed.cluster.shared::cluster.u64 [%0], %1;"
                 :: "r"(addr), "l"(v) : "memory");
}
__device__ __forceinline__ unsigned long long poll_ld(uint32_t addr) {
    unsigned long long v;
    asm volatile("ld.relaxed.cluster.shared::cta.u64 %0, [%1];"
                 : "=l"(v) : "r"(addr) : "memory");
    return v;
}

// ---------------------------------------------------------------------------
// Fused kernel. Blocks [0,32): FPS (frozen R14 protocol @512 threads, with
// paired poll loads — two independent LDS per spin loop, 5 loop-exits
// instead of 7). Blocks [32, 32+4096): KNN for (b = kidx&7, gq = kidx>>3),
// gated on a per-batch release/acquire progress counter (overlaps FPS).
// Role boundary 32 divisible by FPS_CLUSTER => every cluster homogeneous.
// ---------------------------------------------------------------------------
__global__ void __cluster_dims__(FPS_CLUSTER, 1, 1) __launch_bounds__(FT, 2)
fused_kernel(const float* __restrict__ x, float* __restrict__ out_neigh,
             float* __restrict__ out_cen) {
    extern __shared__ uint32_t skey[];          // KNN: NPTS keys (64 KB)
    __shared__ uint32_t s_wval[FT / 32];
    __shared__ int      s_widx[FT / 32];
    __shared__ uint32_t sel[KNN];
    __shared__ uint32_t s_win;
    __shared__ unsigned long long rslot[2][FPS_CLUSTER][4];

    int bx = blockIdx.x;
    int t = threadIdx.x, w = t >> 5, lane = t & 31;

    if (bx < NFPSBLK) {
        // =================== FPS role (frozen protocol) ===================
        uint32_t rank;
        asm("mov.u32 %0, %%cluster_ctarank;" : "=r"(rank));
        int b = bx / FPS_CLUSTER;
        const float4* pts = g_pts + (size_t)b * NPTS;
        int base = (int)rank * FPS_CHUNK + t * FPS_PPT;

        if (t < 2 * FPS_CLUSTER * 4) ((unsigned long long*)rslot)[t] = ~0ull;

        const uint32_t MD0 = __float_as_uint(1e10f);
        unsigned long long pxp[FPS_PAIRS], pyp[FPS_PAIRS], pzp[FPS_PAIRS];
        uint32_t md[FPS_PPT];
#pragma unroll
        for (int j = 0; j < FPS_PAIRS; j++) {
            float4 p0 = pts[base + 2 * j];
            float4 p1 = pts[base + 2 * j + 1];
            pxp[j] = pack2(p0.x, p1.x);
            pyp[j] = pack2(p0.y, p1.y);
            pzp[j] = pack2(p0.z, p1.z);
            md[2 * j] = MD0;
            md[2 * j + 1] = MD0;
        }

        float4 p00 = pts[0];
        float lx = p00.x, ly = p00.y, lz = p00.z;
        float* cout = g_centers + (size_t)b * NGROUP * 3;
        if (rank == 0 && t == 0) {
            cout[0] = lx; cout[1] = ly; cout[2] = lz;
            int one = 1;
            asm volatile("st.release.gpu.b32 [%0], %1;"
                         :: "l"(&g_prog[b]), "r"(one) : "memory");
        }

        asm volatile("barrier.cluster.arrive.aligned;" ::: "memory");
        asm volatile("barrier.cluster.wait.aligned;" ::: "memory");

        const int my_rk = lane >> 2;
        const int my_wd = lane & 3;

        for (int g = 1; g < NGROUP; g++) {
            int p = g & 1;
            unsigned long long tag = ((unsigned long long)(uint32_t)g) << 32;
            unsigned long long nlx2 = pack2(-lx, -lx);
            unsigned long long nly2 = pack2(-ly, -ly);
            unsigned long long nlz2 = pack2(-lz, -lz);
            uint32_t bv = 0; int bk = base;
#pragma unroll
            for (int j = 0; j < FPS_PAIRS; j++) {
                unsigned long long dx2 = addx2(pxp[j], nlx2);
                unsigned long long dy2 = addx2(pyp[j], nly2);
                unsigned long long dz2 = addx2(pzp[j], nlz2);
                unsigned long long dd  = addx2(addx2(mulx2(dx2, dx2), mulx2(dy2, dy2)),
                                               mulx2(dz2, dz2));
                uint32_t d0 = (uint32_t)dd, d1 = (uint32_t)(dd >> 32);
                uint32_t m0 = umin(md[2 * j], d0);
                md[2 * j] = m0;
                if (m0 > bv) { bv = m0; bk = base + 2 * j; }
                uint32_t m1 = umin(md[2 * j + 1], d1);
                md[2 * j + 1] = m1;
                if (m1 > bv) { bv = m1; bk = base + 2 * j + 1; }
            }
            uint32_t wv = __reduce_max_sync(0xFFFFFFFFu, bv);
            uint32_t mm = __ballot_sync(0xFFFFFFFFu, bv == wv);
            int leader = __ffs((int)mm) - 1;
            int wi = __shfl_sync(0xFFFFFFFFu, bk, leader);
            if (lane == 0) { s_wval[w] = wv; s_widx[w] = wi; }
            __syncthreads();

            if (w == 0) {
                // scan 16 warp winners, ascending warp order (== index order)
                uint32_t cv = s_wval[0]; int ci = s_widx[0];
#pragma unroll
                for (int i = 1; i < FT / 32; i++)
                    if (s_wval[i] > cv) { cv = s_wval[i]; ci = s_widx[i]; }
                float4 cp = pts[ci];
                unsigned long long word;
                if      (my_wd == 0) word = tag | cv;
                else if (my_wd == 1) word = tag | __float_as_uint(cp.x);
                else if (my_wd == 2) word = tag | __float_as_uint(cp.y);
                else                 word = tag | __float_as_uint(cp.z);
                if (lane < 4 * FPS_CLUSTER) {
                    uint32_t la = smem_u32(&rslot[p][rank][my_wd]);
                    dsm_st(mapa_sh(la, (uint32_t)my_rk), word);
                }
            }

            // serial per-rank poll with PAIRED independent loads:
            // each spin fetches (val, x) together; coords phase needs only
            // one more paired spin (y, z). 5 loop-exits instead of 7.
            uint32_t bestv = 0; int bestr = 0; uint32_t bestx = 0;
#pragma unroll
            for (int r = 0; r < FPS_CLUSTER; r++) {
                uint32_t ap = smem_u32(&rslot[p][r][0]);
                unsigned long long w0, w1;
                do {
                    w0 = poll_ld(ap);
                    w1 = poll_ld(ap + 8);
                } while (((uint32_t)(w0 >> 32) != (uint32_t)g) ||
                         ((uint32_t)(w1 >> 32) != (uint32_t)g));
                uint32_t v = (uint32_t)w0;
                if (v > bestv) { bestv = v; bestr = r; bestx = (uint32_t)w1; }
            }
            {
                uint32_t ab = smem_u32(&rslot[p][bestr][0]);
                unsigned long long w2, w3;
                do {
                    w2 = poll_ld(ab + 16);
                    w3 = poll_ld(ab + 24);
                } while (((uint32_t)(w2 >> 32) != (uint32_t)g) ||
                         ((uint32_t)(w3 >> 32) != (uint32_t)g));
                lx = __uint_as_float(bestx);
                ly = __uint_as_float((uint32_t)w2);
                lz = __uint_as_float((uint32_t)w3);
            }
            if (rank == 0 && t == 0) {
                cout[3 * g] = lx; cout[3 * g + 1] = ly; cout[3 * g + 2] = lz;
                int gp = g + 1;
                asm volatile("st.release.gpu.b32 [%0], %1;"
                             :: "l"(&g_prog[b]), "r"(gp) : "memory");
            }
        }
        return;
    }

    // ====================== KNN role (byte-identical R15 body) ==============
    int kidx = bx - NFPSBLK;
    int b  = kidx & (BATCH - 1);
    int gq = kidx >> 3;

    // gate: wait until center gq for batch b has been published
    if (t == 0) {
        for (;;) {
            int v;
            asm volatile("ld.acquire.gpu.b32 %0, [%1];"
                         : "=r"(v) : "l"(&g_prog[b]) : "memory");
            if (v > gq) break;
            __nanosleep(1024);
        }
    }
    __syncthreads();

    const float4* pts = g_pts + (size_t)b * NPTS;
    const float* c3 = g_centers + ((size_t)b * NGROUP + gq) * 3;
    float cx = c3[0], cy = c3[1], cz = c3[2];
    float cc = __fadd_rn(__fadd_rn(__fmul_rn(cx, cx), __fmul_rn(cy, cy)),
                         __fmul_rn(cz, cz));

    uint32_t tk = 0xFFFFFFFFu, ti = 0xFFFFFFFFu;
#pragma unroll
    for (int kk = 0; kk < KPT; kk++) {
        int i = kk * FT + t;
        float4 p = pts[i];
        float dot = __fmaf_rn(cz, p.z, __fmaf_rn(cy, p.y, __fmul_rn(cx, p.x)));
        float d2  = __fsub_rn(__fadd_rn(cc, p.w), __fmul_rn(2.0f, dot));
        uint32_t u = __float_as_uint(d2);
        uint32_t o = u ^ (uint32_t)(((int)u >> 31) | 0x80000000);
        skey[i] = o;
        if (o < tk) { tk = o; ti = (uint32_t)i; }
    }
    {
        uint32_t rk = tk, ri = ti;
#pragma unroll
        for (int off = 16; off > 0; off >>= 1) {
            uint32_t ok = __shfl_down_sync(0xFFFFFFFFu, rk, off);
            uint32_t oi = __shfl_down_sync(0xFFFFFFFFu, ri, off);
            if (ok < rk || (ok == rk && oi < ri)) { rk = ok; ri = oi; }
        }
        if (lane == 0) { s_wval[w] = rk; s_widx[w] = (int)ri; }
    }
    __syncthreads();

    for (int j = 0; j < KNN; j++) {
        if (w == 0) {
            uint32_t ak = (lane < FT / 32) ? s_wval[lane] : 0xFFFFFFFFu;
            uint32_t ai = (lane < FT / 32) ? (uint32_t)s_widx[lane] : 0xFFFFFFFFu;
#pragma unroll
            for (int off = 16; off > 0; off >>= 1) {
                uint32_t ok = __shfl_down_sync(0xFFFFFFFFu, ak, off);
                uint32_t oi = __shfl_down_sync(0xFFFFFFFFu, ai, off);
                if (ok < ak || (ok == ak && oi < ai)) { ak = ok; ai = oi; }
            }
            if (lane == 0) { sel[j] = ai; s_win = ai; }
        }
        __syncthreads();
        uint32_t widx = s_win;
        int owner = (int)(widx & (FT - 1));
        if (t == owner) {
            skey[widx] = 0xFFFFFFFFu;
            tk = 0xFFFFFFFFu; ti = 0xFFFFFFFFu;
#pragma unroll
            for (int kk = 0; kk < KPT; kk++) {
                int i = kk * FT + t;
                uint32_t o = skey[i];
                if (o < tk) { tk = o; ti = (uint32_t)i; }
            }
        }
        if (w == (owner >> 5)) {
            uint32_t rk = tk, ri = ti;
#pragma unroll
            for (int off = 16; off > 0; off >>= 1) {
                uint32_t ok = __shfl_down_sync(0xFFFFFFFFu, rk, off);
                uint32_t oi = __shfl_down_sync(0xFFFFFFFFu, ri, off);
                if (ok < rk || (ok == rk && oi < ri)) { rk = ok; ri = oi; }
            }
            if (lane == 0) { s_wval[w] = rk; s_widx[w] = (int)ri; }
        }
        __syncthreads();
    }

    if (t < KNN * CH) {
        int jj = t / CH, c = t % CH;
        uint32_t idx = sel[jj];
        float v = x[((size_t)b * NPTS + idx) * CH + c];
        if (c >= 4 && c < 7) {
            float cv = (c == 4) ? cx : ((c == 5) ? cy : cz);
            v = __fadd_rn(v, -cv);
        }
        out_neigh[(((size_t)b * NGROUP + gq) * KNN + jj) * CH + c] = v;
    } else if (t >= KNN * CH && t < KNN * CH + 3 && out_cen != nullptr) {
        int c = t - KNN * CH;
        out_cen[((size_t)b * NGROUP + gq) * 3 + c] = c3[c];
    }
}

extern "C" void kernel_launch(void* const* d_in, const int* in_sizes, int n_in,
                              void* d_out, int out_size) {
    const float* x = (const float*)d_in[0];
    float* out = (float*)d_out;
    float* out_cen = ((size_t)out_size >= NEIGH_ELEMS + CEN_ELEMS)
                         ? (out + NEIGH_ELEMS) : nullptr;

    cudaFuncSetAttribute(fused_kernel, cudaFuncAttributeMaxDynamicSharedMemorySize,
                         NPTS * sizeof(uint32_t));

    prep_kernel<<<(BATCH * NPTS + 255) / 256, 256>>>(x);
    fused_kernel<<<NFPSBLK + BATCH * NGROUP, FT, NPTS * sizeof(uint32_t)>>>(
        x, out, out_cen);
}